// round 11
// baseline (speedup 1.0000x reference)
#include <cuda_runtime.h>
#include <cuda_fp16.h>

// ---------------------------------------------------------------------------
// Hetero-GNN (5 hetero_conv layers) over N=100000 nodes.
// R11 = R10 (fused layers, 678us) + a DUMMY fused_hidden launch at graph
//       index 3 (25k nodes, dead output) so ncu's fixed capture slot lands on
//       the dominant kernel class. Measurement round: output unaffected.
// ---------------------------------------------------------------------------

#define N_NODES 100000

// Scratch (device globals; no allocation allowed; zero-initialized at load)
__device__ float g_h    [N_NODES * 32];
__device__ float g_h2   [N_NODES * 32];
__device__ float g_dummy[N_NODES * 32];

__device__ int g_deg_t[N_NODES];
__device__ int g_deg_i[N_NODES];
__device__ int g_rpt  [N_NODES + 1];
__device__ int g_rpi  [N_NODES + 1];
__device__ int g_bsum_t[1024];
__device__ int g_bsum_i[1024];
__device__ int g_col_t[100000];
__device__ int g_col_i[3200000];

// ---------------------------------------------------------------------------
// CSR build (identical to champion)
// ---------------------------------------------------------------------------
__global__ void zero2_kernel(int* __restrict__ a, int* __restrict__ b, int n) {
    int i = blockIdx.x * blockDim.x + threadIdx.x;
    if (i < n) { a[i] = 0; b[i] = 0; }
}

__global__ void count_kernel(const int* __restrict__ dst, int E, int* __restrict__ deg) {
    int i = blockIdx.x * blockDim.x + threadIdx.x;
    if (i < E) atomicAdd(&deg[dst[i]], 1);
}

__global__ void scan_p1(const int* __restrict__ deg, int* __restrict__ rowptr,
                        int* __restrict__ bsum, int n) {
    __shared__ int sh[1024];
    int i = blockIdx.x * 1024 + threadIdx.x;
    int v = (i < n) ? deg[i] : 0;
    sh[threadIdx.x] = v;
    __syncthreads();
    for (int off = 1; off < 1024; off <<= 1) {
        int t = (threadIdx.x >= off) ? sh[threadIdx.x - off] : 0;
        __syncthreads();
        sh[threadIdx.x] += t;
        __syncthreads();
    }
    if (i < n) rowptr[i] = sh[threadIdx.x] - v;
    if (threadIdx.x == 1023) bsum[blockIdx.x] = sh[1023];
}

__global__ void scan_p2(int* __restrict__ bsum, int nb) {
    __shared__ int sh[1024];
    int v = (threadIdx.x < nb) ? bsum[threadIdx.x] : 0;
    sh[threadIdx.x] = v;
    __syncthreads();
    for (int off = 1; off < 1024; off <<= 1) {
        int t = (threadIdx.x >= off) ? sh[threadIdx.x - off] : 0;
        __syncthreads();
        sh[threadIdx.x] += t;
        __syncthreads();
    }
    if (threadIdx.x < nb) bsum[threadIdx.x] = sh[threadIdx.x] - v;
}

__global__ void scan_p3(int* __restrict__ rowptr, const int* __restrict__ bsum,
                        int* __restrict__ cursor, int n, int E) {
    int i = blockIdx.x * blockDim.x + threadIdx.x;
    if (i < n) {
        int v = rowptr[i] + bsum[i >> 10];
        rowptr[i] = v;
        cursor[i] = v;
    }
    if (i == 0) rowptr[n] = E;
}

__global__ void fill_kernel(const int* __restrict__ src, const int* __restrict__ dst,
                            int E, int* __restrict__ cursor, int* __restrict__ col) {
    int i = blockIdx.x * blockDim.x + threadIdx.x;
    if (i < E) {
        int d = dst[i];
        int p = atomicAdd(&cursor[d], 1);
        col[p] = src[i];
    }
}

// ---------------------------------------------------------------------------
// Fused HEAD layer: 6 -> 32.
// ---------------------------------------------------------------------------
__global__ void fused_head(const float* __restrict__ x,
                           const int* __restrict__ rpt, const int* __restrict__ colt,
                           const int* __restrict__ rpi, const int* __restrict__ coli,
                           const float* __restrict__ Wt, const float* __restrict__ Wi,
                           const float* __restrict__ Wr, const float* __restrict__ b,
                           float* __restrict__ hout, int n) {
    __shared__ float sWt[6 * 32], sWi[6 * 32], sWr[6 * 32], sB[32];
    for (int i = threadIdx.x; i < 6 * 32; i += blockDim.x) {
        sWt[i] = Wt[i]; sWi[i] = Wi[i]; sWr[i] = Wr[i];
    }
    if (threadIdx.x < 32) sB[threadIdx.x] = b[threadIdx.x];
    __syncthreads();

    int node = blockIdx.x * (blockDim.x >> 5) + (threadIdx.x >> 5);
    if (node >= n) return;
    int lane = threadIdx.x & 31;

    float sT = 0.f, sM = 0.f;

    int b0 = rpt[node], e0 = rpt[node + 1];
    for (int e = b0; e < e0; e++) {
        int s = colt[e];
        if (lane < 6) sT += x[s * 6 + lane];
    }

    int b1 = rpi[node], e1 = rpi[node + 1];
    int e = b1;
    for (; e + 32 <= e1; e += 32) {
        int idx = coli[e + lane];
#pragma unroll
        for (int k = 0; k < 32; k++) {
            int s = __shfl_sync(0xffffffffu, idx, k);
            if (lane < 6) sM += x[s * 6 + lane];
        }
    }
    if (e < e1) {
        int rem = e1 - e;
        int idx = (lane < rem) ? coli[e + lane] : 0;
        for (int k = 0; k < rem; k++) {
            int s = __shfl_sync(0xffffffffu, idx, k);
            if (lane < 6) sM += x[s * 6 + lane];
        }
    }
    sM *= 1.0f / fmaxf((float)(e1 - b1), 1.0f);

    float xv = (lane < 6) ? x[node * 6 + lane] : 0.f;

    float acc = sB[lane];
#pragma unroll
    for (int ci = 0; ci < 6; ci++) {
        float t = __shfl_sync(0xffffffffu, sT, ci);
        float m = __shfl_sync(0xffffffffu, sM, ci);
        float r = __shfl_sync(0xffffffffu, xv, ci);
        acc += t * sWt[ci * 32 + lane] + m * sWi[ci * 32 + lane] + r * sWr[ci * 32 + lane];
    }
    hout[node * 32 + lane] = fmaxf(acc, 0.f);
}

// ---------------------------------------------------------------------------
// Fused HIDDEN layer: 32 -> 32 with residual.
// ---------------------------------------------------------------------------
__global__ void fused_hidden(const float* __restrict__ h,
                             const int* __restrict__ rpt, const int* __restrict__ colt,
                             const int* __restrict__ rpi, const int* __restrict__ coli,
                             const float* __restrict__ Wt, const float* __restrict__ Wi,
                             const float* __restrict__ Wr, const float* __restrict__ b,
                             float* __restrict__ hout, int n) {
    __shared__ float sWt[32 * 32], sWi[32 * 32], sWr[32 * 32], sB[32];
    for (int i = threadIdx.x; i < 32 * 32; i += blockDim.x) {
        sWt[i] = Wt[i]; sWi[i] = Wi[i]; sWr[i] = Wr[i];
    }
    if (threadIdx.x < 32) sB[threadIdx.x] = b[threadIdx.x];
    __syncthreads();

    int node = blockIdx.x * (blockDim.x >> 5) + (threadIdx.x >> 5);
    if (node >= n) return;
    int lane = threadIdx.x & 31;

    float sT = 0.f, sM = 0.f;

    int b0 = rpt[node], e0 = rpt[node + 1];
    for (int e = b0; e < e0; e++) {
        int s = colt[e];
        sT += h[s * 32 + lane];
    }

    int b1 = rpi[node], e1 = rpi[node + 1];
    int e = b1;
    for (; e + 32 <= e1; e += 32) {
        int idx = coli[e + lane];
#pragma unroll
        for (int k = 0; k < 32; k++) {
            int s = __shfl_sync(0xffffffffu, idx, k);
            sM += h[s * 32 + lane];
        }
    }
    if (e < e1) {
        int rem = e1 - e;
        int idx = (lane < rem) ? coli[e + lane] : 0;
        for (int k = 0; k < rem; k++) {
            int s = __shfl_sync(0xffffffffu, idx, k);
            sM += h[s * 32 + lane];
        }
    }
    sM *= 1.0f / fmaxf((float)(e1 - b1), 1.0f);

    float hv = h[node * 32 + lane];

    float acc = sB[lane];
#pragma unroll
    for (int ci = 0; ci < 32; ci++) {
        float t = __shfl_sync(0xffffffffu, sT, ci);
        float m = __shfl_sync(0xffffffffu, sM, ci);
        float r = __shfl_sync(0xffffffffu, hv, ci);
        acc += t * sWt[ci * 32 + lane] + m * sWi[ci * 32 + lane] + r * sWr[ci * 32 + lane];
    }
    hout[node * 32 + lane] = fmaxf(acc, 0.f) + hv;   // residual
}

// ---------------------------------------------------------------------------
// Fused LAST layer: 32 -> 64.
// ---------------------------------------------------------------------------
__global__ void fused_last(const float* __restrict__ h,
                           const int* __restrict__ rpt, const int* __restrict__ colt,
                           const int* __restrict__ rpi, const int* __restrict__ coli,
                           const float* __restrict__ Wt, const float* __restrict__ Wi,
                           const float* __restrict__ Wr, const float* __restrict__ b,
                           const float* __restrict__ Wp,
                           float* __restrict__ out, int n) {
    __shared__ float sWt[32 * 64], sWi[32 * 64], sWr[32 * 64], sWp[32 * 64], sB[64];
    for (int i = threadIdx.x; i < 32 * 64; i += blockDim.x) {
        sWt[i] = Wt[i]; sWi[i] = Wi[i]; sWr[i] = Wr[i]; sWp[i] = Wp[i];
    }
    if (threadIdx.x < 64) sB[threadIdx.x] = b[threadIdx.x];
    __syncthreads();

    int node = blockIdx.x * (blockDim.x >> 5) + (threadIdx.x >> 5);
    if (node >= n) return;
    int lane = threadIdx.x & 31;

    float sT = 0.f, sM = 0.f;

    int b0 = rpt[node], e0 = rpt[node + 1];
    for (int e = b0; e < e0; e++) {
        int s = colt[e];
        sT += h[s * 32 + lane];
    }

    int b1 = rpi[node], e1 = rpi[node + 1];
    int e = b1;
    for (; e + 32 <= e1; e += 32) {
        int idx = coli[e + lane];
#pragma unroll
        for (int k = 0; k < 32; k++) {
            int s = __shfl_sync(0xffffffffu, idx, k);
            sM += h[s * 32 + lane];
        }
    }
    if (e < e1) {
        int rem = e1 - e;
        int idx = (lane < rem) ? coli[e + lane] : 0;
        for (int k = 0; k < rem; k++) {
            int s = __shfl_sync(0xffffffffu, idx, k);
            sM += h[s * 32 + lane];
        }
    }
    sM *= 1.0f / fmaxf((float)(e1 - b1), 1.0f);

    float hv = h[node * 32 + lane];

    float acc0 = sB[lane], acc1 = sB[lane + 32];
    float p0 = 0.f, p1 = 0.f;
#pragma unroll
    for (int ci = 0; ci < 32; ci++) {
        float t = __shfl_sync(0xffffffffu, sT, ci);
        float m = __shfl_sync(0xffffffffu, sM, ci);
        float r = __shfl_sync(0xffffffffu, hv, ci);
        acc0 += t * sWt[ci * 64 + lane]      + m * sWi[ci * 64 + lane]      + r * sWr[ci * 64 + lane];
        acc1 += t * sWt[ci * 64 + lane + 32] + m * sWi[ci * 64 + lane + 32] + r * sWr[ci * 64 + lane + 32];
        p0   += r * sWp[ci * 64 + lane];
        p1   += r * sWp[ci * 64 + lane + 32];
    }
    out[node * 64 + lane]      = fmaxf(acc0, 0.f) + p0;
    out[node * 64 + lane + 32] = fmaxf(acc1, 0.f) + p1;
}

// ---------------------------------------------------------------------------
// Launch
// ---------------------------------------------------------------------------
extern "C" void kernel_launch(void* const* d_in, const int* in_sizes, int n_in,
                              void* d_out, int out_size) {
    const float* x        = (const float*)d_in[0];
    const int*   ei_t     = (const int*)d_in[1];
    const int*   ei_i     = (const int*)d_in[2];
    const float* head_Wt  = (const float*)d_in[3];
    const float* head_Wi  = (const float*)d_in[4];
    const float* head_Wr  = (const float*)d_in[5];
    const float* head_b   = (const float*)d_in[6];
    const float* blk_Wt   = (const float*)d_in[7];
    const float* blk_Wi   = (const float*)d_in[8];
    const float* blk_Wr   = (const float*)d_in[9];
    const float* blk_b    = (const float*)d_in[10];
    const float* last_Wt  = (const float*)d_in[11];
    const float* last_Wi  = (const float*)d_in[12];
    const float* last_Wr  = (const float*)d_in[13];
    const float* last_b   = (const float*)d_in[14];
    const float* last_proj= (const float*)d_in[15];

    const int n  = in_sizes[0] / 6;      // 100000
    const int Et = in_sizes[1] / 2;      // 100000
    const int Ei = in_sizes[2] / 2;      // 3200000

    float *h, *h2, *dmy;
    int *degt, *degi, *rpt, *rpi, *colt, *coli, *bst, *bsi;
    cudaGetSymbolAddress((void**)&h,    g_h);
    cudaGetSymbolAddress((void**)&h2,   g_h2);
    cudaGetSymbolAddress((void**)&dmy,  g_dummy);
    cudaGetSymbolAddress((void**)&degt, g_deg_t);
    cudaGetSymbolAddress((void**)&degi, g_deg_i);
    cudaGetSymbolAddress((void**)&rpt,  g_rpt);
    cudaGetSymbolAddress((void**)&rpi,  g_rpi);
    cudaGetSymbolAddress((void**)&bst,  g_bsum_t);
    cudaGetSymbolAddress((void**)&bsi,  g_bsum_i);
    cudaGetSymbolAddress((void**)&colt, g_col_t);
    cudaGetSymbolAddress((void**)&coli, g_col_i);

    const int T = 256;
    int nodeBlocks = (n * 32 + T - 1) / T;
    int nb = (n + 1023) / 1024;

    // Launch 0-2: zero + counts
    zero2_kernel<<<(n + T - 1) / T, T>>>(degt, degi, n);
    count_kernel<<<(Et + T - 1) / T, T>>>(ei_t + Et, Et, degt);
    count_kernel<<<(Ei + T - 1) / T, T>>>(ei_i + Ei, Ei, degi);

    // Launch 3 (ncu capture slot): DUMMY fused_hidden on 25k nodes.
    // Reads CSR/h persisted from the previous replay (zero-init => safe on
    // first call: all rowptrs 0 -> zero-trip loops). Output g_dummy is dead.
    {
        const int nd = 25000;
        int db = (nd * 32 + T - 1) / T;
        fused_hidden<<<db, T>>>(h, rpt, colt, rpi, coli,
                                blk_Wt, blk_Wi, blk_Wr, blk_b, dmy, nd);
    }

    // CSR build continues (identical work)
    scan_p1<<<nb, 1024>>>(degt, rpt, bst, n);
    scan_p1<<<nb, 1024>>>(degi, rpi, bsi, n);
    scan_p2<<<1, 1024>>>(bst, nb);
    scan_p2<<<1, 1024>>>(bsi, nb);
    scan_p3<<<(n + T) / T, T>>>(rpt, bst, degt, n, Et);
    scan_p3<<<(n + T) / T, T>>>(rpi, bsi, degi, n, Ei);
    fill_kernel<<<(Et + T - 1) / T, T>>>(ei_t, ei_t + Et, Et, degt, colt);
    fill_kernel<<<(Ei + T - 1) / T, T>>>(ei_i, ei_i + Ei, Ei, degi, coli);

    // --- head: 6 -> 32 (fused) ---
    fused_head<<<nodeBlocks, T>>>(x, rpt, colt, rpi, coli,
                                  head_Wt, head_Wi, head_Wr, head_b, h, n);

    // --- 3 residual blocks: 32 -> 32 (fused) ---
    for (int i = 0; i < 3; i++) {
        fused_hidden<<<nodeBlocks, T>>>(h, rpt, colt, rpi, coli,
                                        blk_Wt + i * 32 * 32, blk_Wi + i * 32 * 32,
                                        blk_Wr + i * 32 * 32, blk_b + i * 32,
                                        h2, n);
        float* tmp = h; h = h2; h2 = tmp;
    }

    // --- last: 32 -> 64 (fused) ---
    fused_last<<<nodeBlocks, T>>>(h, rpt, colt, rpi, coli,
                                  last_Wt, last_Wi, last_Wr, last_b, last_proj,
                                  (float*)d_out, n);
}

// round 12
// speedup vs baseline: 1.2127x; 1.2127x over previous
#include <cuda_runtime.h>
#include <cuda_fp16.h>

// ---------------------------------------------------------------------------
// Hetero-GNN (5 hetero_conv layers) over N=100000 nodes.
// R12: MIO-lean fused layers.
//  - Gather: 4 edges/warp-iteration (8-lane groups, float4 rows), NO per-edge
//    shfl; group partials merged once per node.
//  - Combine: 4 nodes/warp, packed float4 weights shared across nodes,
//    per-node vectors staged in smem (1 broadcast LDS per ci per node).
// Evidence: R11 probe showed L1TEX/MIO = 66.5% is the wall (L2/DRAM ~1.6%).
// ---------------------------------------------------------------------------

#define N_NODES 100000

__device__ float g_h    [N_NODES * 32];
__device__ float g_h2   [N_NODES * 32];
__device__ float g_x8   [N_NODES * 8];     // x padded 6 -> 8 floats
__device__ float g_dummy[N_NODES * 32];

__device__ int g_deg_t[N_NODES];
__device__ int g_deg_i[N_NODES];
__device__ int g_rpt  [N_NODES + 1];
__device__ int g_rpi  [N_NODES + 1];
__device__ int g_bsum_t[1024];
__device__ int g_bsum_i[1024];
__device__ int g_col_t[100000];
__device__ int g_col_i[3200000];

// ---------------------------------------------------------------------------
// CSR build (identical to champion)
// ---------------------------------------------------------------------------
__global__ void zero2_kernel(int* __restrict__ a, int* __restrict__ b, int n) {
    int i = blockIdx.x * blockDim.x + threadIdx.x;
    if (i < n) { a[i] = 0; b[i] = 0; }
}

__global__ void count_kernel(const int* __restrict__ dst, int E, int* __restrict__ deg) {
    int i = blockIdx.x * blockDim.x + threadIdx.x;
    if (i < E) atomicAdd(&deg[dst[i]], 1);
}

__global__ void scan_p1(const int* __restrict__ deg, int* __restrict__ rowptr,
                        int* __restrict__ bsum, int n) {
    __shared__ int sh[1024];
    int i = blockIdx.x * 1024 + threadIdx.x;
    int v = (i < n) ? deg[i] : 0;
    sh[threadIdx.x] = v;
    __syncthreads();
    for (int off = 1; off < 1024; off <<= 1) {
        int t = (threadIdx.x >= off) ? sh[threadIdx.x - off] : 0;
        __syncthreads();
        sh[threadIdx.x] += t;
        __syncthreads();
    }
    if (i < n) rowptr[i] = sh[threadIdx.x] - v;
    if (threadIdx.x == 1023) bsum[blockIdx.x] = sh[1023];
}

__global__ void scan_p2(int* __restrict__ bsum, int nb) {
    __shared__ int sh[1024];
    int v = (threadIdx.x < nb) ? bsum[threadIdx.x] : 0;
    sh[threadIdx.x] = v;
    __syncthreads();
    for (int off = 1; off < 1024; off <<= 1) {
        int t = (threadIdx.x >= off) ? sh[threadIdx.x - off] : 0;
        __syncthreads();
        sh[threadIdx.x] += t;
        __syncthreads();
    }
    if (threadIdx.x < nb) bsum[threadIdx.x] = sh[threadIdx.x] - v;
}

__global__ void scan_p3(int* __restrict__ rowptr, const int* __restrict__ bsum,
                        int* __restrict__ cursor, int n, int E) {
    int i = blockIdx.x * blockDim.x + threadIdx.x;
    if (i < n) {
        int v = rowptr[i] + bsum[i >> 10];
        rowptr[i] = v;
        cursor[i] = v;
    }
    if (i == 0) rowptr[n] = E;
}

__global__ void fill_kernel(const int* __restrict__ src, const int* __restrict__ dst,
                            int E, int* __restrict__ cursor, int* __restrict__ col) {
    int i = blockIdx.x * blockDim.x + threadIdx.x;
    if (i < E) {
        int d = dst[i];
        int p = atomicAdd(&cursor[d], 1);
        col[p] = src[i];
    }
}

// Pad x [N,6] -> x8 [N,8] (zeros in slots 6,7)
__global__ void repack_x8(const float* __restrict__ x, float* __restrict__ x8, int n) {
    int i = blockIdx.x * blockDim.x + threadIdx.x;
    if (i < n * 8) {
        int node = i >> 3, c = i & 7;
        x8[i] = (c < 6) ? x[node * 6 + c] : 0.f;
    }
}

// ---------------------------------------------------------------------------
// Fused HIDDEN layer (32->32, residual). 4 nodes/warp, 8 warps/block.
// ---------------------------------------------------------------------------
__global__ void fused_hidden2(const float* __restrict__ h,
                              const int* __restrict__ rpt, const int* __restrict__ colt,
                              const int* __restrict__ rpi, const int* __restrict__ coli,
                              const float* __restrict__ Wt, const float* __restrict__ Wi,
                              const float* __restrict__ Wr, const float* __restrict__ b,
                              float* __restrict__ hout, int n) {
    __shared__ float4 sW4[32 * 32];        // (Wt, Wi, Wr, 0) per [ci][lane]
    __shared__ float4 sV[8 * 4 * 32];      // per-warp: 4 nodes x 32 x (t,m,r,0)
    __shared__ float  sB[32];

    for (int i = threadIdx.x; i < 32 * 32; i += blockDim.x) {
        int ci = i >> 5, l = i & 31;
        sW4[i] = make_float4(Wt[ci * 32 + l], Wi[ci * 32 + l], Wr[ci * 32 + l], 0.f);
    }
    if (threadIdx.x < 32) sB[threadIdx.x] = b[threadIdx.x];
    __syncthreads();

    int warp = threadIdx.x >> 5, lane = threadIdx.x & 31;
    int node0 = (blockIdx.x * 8 + warp) * 4;
    if (node0 >= n) return;
    int g = lane >> 3, c = lane & 7;
    const float4* h4 = (const float4*)h;
    float4* vbase = &sV[warp * 128];

#pragma unroll
    for (int j = 0; j < 4; j++) {
        int node = node0 + j;
        if (node >= n) break;

        float4 aT = make_float4(0.f, 0.f, 0.f, 0.f);
        float4 aM = make_float4(0.f, 0.f, 0.f, 0.f);

        int b0 = rpt[node], e0 = rpt[node + 1];
        for (int e = b0; e < e0; e += 4) {
            int ei = e + g;
            int ec = (ei < e0) ? ei : (e0 - 1);
            int s = colt[ec];
            float4 v = h4[s * 8 + c];
            if (ei < e0) { aT.x += v.x; aT.y += v.y; aT.z += v.z; aT.w += v.w; }
        }

        int b1 = rpi[node], e1 = rpi[node + 1];
        for (int e = b1; e < e1; e += 4) {
            int ei = e + g;
            int ec = (ei < e1) ? ei : (e1 - 1);
            int s = coli[ec];
            float4 v = h4[s * 8 + c];
            if (ei < e1) { aM.x += v.x; aM.y += v.y; aM.z += v.z; aM.w += v.w; }
        }

        // merge the 4 edge-groups
#pragma unroll
        for (int off = 8; off <= 16; off <<= 1) {
            aT.x += __shfl_xor_sync(0xffffffffu, aT.x, off);
            aT.y += __shfl_xor_sync(0xffffffffu, aT.y, off);
            aT.z += __shfl_xor_sync(0xffffffffu, aT.z, off);
            aT.w += __shfl_xor_sync(0xffffffffu, aT.w, off);
            aM.x += __shfl_xor_sync(0xffffffffu, aM.x, off);
            aM.y += __shfl_xor_sync(0xffffffffu, aM.y, off);
            aM.z += __shfl_xor_sync(0xffffffffu, aM.z, off);
            aM.w += __shfl_xor_sync(0xffffffffu, aM.w, off);
        }
        float invd = 1.0f / fmaxf((float)(e1 - b1), 1.0f);
        aM.x *= invd; aM.y *= invd; aM.z *= invd; aM.w *= invd;

        if (lane < 8) {
            float4 hv = h4[node * 8 + lane];
            vbase[j * 32 + lane * 4 + 0] = make_float4(aT.x, aM.x, hv.x, 0.f);
            vbase[j * 32 + lane * 4 + 1] = make_float4(aT.y, aM.y, hv.y, 0.f);
            vbase[j * 32 + lane * 4 + 2] = make_float4(aT.z, aM.z, hv.z, 0.f);
            vbase[j * 32 + lane * 4 + 3] = make_float4(aT.w, aM.w, hv.w, 0.f);
        }
    }
    __syncwarp();

    float acc0 = sB[lane], acc1 = sB[lane], acc2 = sB[lane], acc3 = sB[lane];
#pragma unroll
    for (int ci = 0; ci < 32; ci++) {
        float4 w = sW4[ci * 32 + lane];
        float4 v0 = vbase[0 * 32 + ci];
        float4 v1 = vbase[1 * 32 + ci];
        float4 v2 = vbase[2 * 32 + ci];
        float4 v3 = vbase[3 * 32 + ci];
        acc0 += v0.x * w.x + v0.y * w.y + v0.z * w.z;
        acc1 += v1.x * w.x + v1.y * w.y + v1.z * w.z;
        acc2 += v2.x * w.x + v2.y * w.y + v2.z * w.z;
        acc3 += v3.x * w.x + v3.y * w.y + v3.z * w.z;
    }
    float accs[4] = {acc0, acc1, acc2, acc3};
#pragma unroll
    for (int j = 0; j < 4; j++) {
        int node = node0 + j;
        if (node < n) {
            float hv = vbase[j * 32 + lane].z;
            hout[node * 32 + lane] = fmaxf(accs[j], 0.f) + hv;
        }
    }
}

// ---------------------------------------------------------------------------
// Fused HEAD layer (6->32). Gathers from padded x8 (32B rows, 16 edge-groups).
// ---------------------------------------------------------------------------
__global__ void fused_head2(const float* __restrict__ x8,
                            const int* __restrict__ rpt, const int* __restrict__ colt,
                            const int* __restrict__ rpi, const int* __restrict__ coli,
                            const float* __restrict__ Wt, const float* __restrict__ Wi,
                            const float* __restrict__ Wr, const float* __restrict__ b,
                            float* __restrict__ hout, int n) {
    __shared__ float4 sW4[6 * 32];         // (Wt, Wi, Wr, 0) per [ci][lane]
    __shared__ float4 sV[8 * 4 * 8];       // per-warp: 4 nodes x 8 x (t,m,r,0)
    __shared__ float  sB[32];

    for (int i = threadIdx.x; i < 6 * 32; i += blockDim.x) {
        int ci = i >> 5, l = i & 31;
        sW4[i] = make_float4(Wt[ci * 32 + l], Wi[ci * 32 + l], Wr[ci * 32 + l], 0.f);
    }
    if (threadIdx.x < 32) sB[threadIdx.x] = b[threadIdx.x];
    __syncthreads();

    int warp = threadIdx.x >> 5, lane = threadIdx.x & 31;
    int node0 = (blockIdx.x * 8 + warp) * 4;
    if (node0 >= n) return;
    int g = lane >> 1, c = lane & 1;       // 16 groups x 2 lanes (float4 pair = 32B row)
    const float4* x4 = (const float4*)x8;
    float4* vbase = &sV[warp * 32];

#pragma unroll
    for (int j = 0; j < 4; j++) {
        int node = node0 + j;
        if (node >= n) break;

        float4 aT = make_float4(0.f, 0.f, 0.f, 0.f);
        float4 aM = make_float4(0.f, 0.f, 0.f, 0.f);

        int b0 = rpt[node], e0 = rpt[node + 1];
        for (int e = b0; e < e0; e += 16) {
            int ei = e + g;
            int ec = (ei < e0) ? ei : (e0 - 1);
            int s = colt[ec];
            float4 v = x4[s * 2 + c];
            if (ei < e0) { aT.x += v.x; aT.y += v.y; aT.z += v.z; aT.w += v.w; }
        }

        int b1 = rpi[node], e1 = rpi[node + 1];
        for (int e = b1; e < e1; e += 16) {
            int ei = e + g;
            int ec = (ei < e1) ? ei : (e1 - 1);
            int s = coli[ec];
            float4 v = x4[s * 2 + c];
            if (ei < e1) { aM.x += v.x; aM.y += v.y; aM.z += v.z; aM.w += v.w; }
        }

        // merge the 16 edge-groups (xor 2,4,8,16)
#pragma unroll
        for (int off = 2; off <= 16; off <<= 1) {
            aT.x += __shfl_xor_sync(0xffffffffu, aT.x, off);
            aT.y += __shfl_xor_sync(0xffffffffu, aT.y, off);
            aT.z += __shfl_xor_sync(0xffffffffu, aT.z, off);
            aT.w += __shfl_xor_sync(0xffffffffu, aT.w, off);
            aM.x += __shfl_xor_sync(0xffffffffu, aM.x, off);
            aM.y += __shfl_xor_sync(0xffffffffu, aM.y, off);
            aM.z += __shfl_xor_sync(0xffffffffu, aM.z, off);
            aM.w += __shfl_xor_sync(0xffffffffu, aM.w, off);
        }
        float invd = 1.0f / fmaxf((float)(e1 - b1), 1.0f);
        aM.x *= invd; aM.y *= invd; aM.z *= invd; aM.w *= invd;

        if (lane < 2) {
            float4 xv = x4[node * 2 + lane];
            vbase[j * 8 + lane * 4 + 0] = make_float4(aT.x, aM.x, xv.x, 0.f);
            vbase[j * 8 + lane * 4 + 1] = make_float4(aT.y, aM.y, xv.y, 0.f);
            vbase[j * 8 + lane * 4 + 2] = make_float4(aT.z, aM.z, xv.z, 0.f);
            vbase[j * 8 + lane * 4 + 3] = make_float4(aT.w, aM.w, xv.w, 0.f);
        }
    }
    __syncwarp();

    float acc0 = sB[lane], acc1 = sB[lane], acc2 = sB[lane], acc3 = sB[lane];
#pragma unroll
    for (int ci = 0; ci < 6; ci++) {
        float4 w = sW4[ci * 32 + lane];
        float4 v0 = vbase[0 * 8 + ci];
        float4 v1 = vbase[1 * 8 + ci];
        float4 v2 = vbase[2 * 8 + ci];
        float4 v3 = vbase[3 * 8 + ci];
        acc0 += v0.x * w.x + v0.y * w.y + v0.z * w.z;
        acc1 += v1.x * w.x + v1.y * w.y + v1.z * w.z;
        acc2 += v2.x * w.x + v2.y * w.y + v2.z * w.z;
        acc3 += v3.x * w.x + v3.y * w.y + v3.z * w.z;
    }
    float accs[4] = {acc0, acc1, acc2, acc3};
#pragma unroll
    for (int j = 0; j < 4; j++) {
        int node = node0 + j;
        if (node < n) hout[node * 32 + lane] = fmaxf(accs[j], 0.f);
    }
}

// ---------------------------------------------------------------------------
// Fused LAST layer (32->64 + projection residual). 4 warps/block (smem).
// ---------------------------------------------------------------------------
__global__ void fused_last2(const float* __restrict__ h,
                            const int* __restrict__ rpt, const int* __restrict__ colt,
                            const int* __restrict__ rpi, const int* __restrict__ coli,
                            const float* __restrict__ Wt, const float* __restrict__ Wi,
                            const float* __restrict__ Wr, const float* __restrict__ b,
                            const float* __restrict__ Wp,
                            float* __restrict__ out, int n) {
    __shared__ float4 sW4a[32 * 32];       // (Wt,Wi,Wr,Wp) for out-ch lane
    __shared__ float4 sW4b[32 * 32];       // (Wt,Wi,Wr,Wp) for out-ch lane+32
    __shared__ float4 sV[4 * 4 * 32];      // 4 warps x 4 nodes x 32 x (t,m,r,0)

    for (int i = threadIdx.x; i < 32 * 32; i += blockDim.x) {
        int ci = i >> 5, l = i & 31;
        sW4a[i] = make_float4(Wt[ci * 64 + l],      Wi[ci * 64 + l],      Wr[ci * 64 + l],      Wp[ci * 64 + l]);
        sW4b[i] = make_float4(Wt[ci * 64 + l + 32], Wi[ci * 64 + l + 32], Wr[ci * 64 + l + 32], Wp[ci * 64 + l + 32]);
    }
    __syncthreads();

    int warp = threadIdx.x >> 5, lane = threadIdx.x & 31;
    int node0 = (blockIdx.x * 4 + warp) * 4;
    if (node0 >= n) return;
    int g = lane >> 3, c = lane & 7;
    const float4* h4 = (const float4*)h;
    float4* vbase = &sV[warp * 128];

    float bias0 = b[lane], bias1 = b[lane + 32];

#pragma unroll
    for (int j = 0; j < 4; j++) {
        int node = node0 + j;
        if (node >= n) break;

        float4 aT = make_float4(0.f, 0.f, 0.f, 0.f);
        float4 aM = make_float4(0.f, 0.f, 0.f, 0.f);

        int b0 = rpt[node], e0 = rpt[node + 1];
        for (int e = b0; e < e0; e += 4) {
            int ei = e + g;
            int ec = (ei < e0) ? ei : (e0 - 1);
            int s = colt[ec];
            float4 v = h4[s * 8 + c];
            if (ei < e0) { aT.x += v.x; aT.y += v.y; aT.z += v.z; aT.w += v.w; }
        }

        int b1 = rpi[node], e1 = rpi[node + 1];
        for (int e = b1; e < e1; e += 4) {
            int ei = e + g;
            int ec = (ei < e1) ? ei : (e1 - 1);
            int s = coli[ec];
            float4 v = h4[s * 8 + c];
            if (ei < e1) { aM.x += v.x; aM.y += v.y; aM.z += v.z; aM.w += v.w; }
        }

#pragma unroll
        for (int off = 8; off <= 16; off <<= 1) {
            aT.x += __shfl_xor_sync(0xffffffffu, aT.x, off);
            aT.y += __shfl_xor_sync(0xffffffffu, aT.y, off);
            aT.z += __shfl_xor_sync(0xffffffffu, aT.z, off);
            aT.w += __shfl_xor_sync(0xffffffffu, aT.w, off);
            aM.x += __shfl_xor_sync(0xffffffffu, aM.x, off);
            aM.y += __shfl_xor_sync(0xffffffffu, aM.y, off);
            aM.z += __shfl_xor_sync(0xffffffffu, aM.z, off);
            aM.w += __shfl_xor_sync(0xffffffffu, aM.w, off);
        }
        float invd = 1.0f / fmaxf((float)(e1 - b1), 1.0f);
        aM.x *= invd; aM.y *= invd; aM.z *= invd; aM.w *= invd;

        if (lane < 8) {
            float4 hv = h4[node * 8 + lane];
            vbase[j * 32 + lane * 4 + 0] = make_float4(aT.x, aM.x, hv.x, 0.f);
            vbase[j * 32 + lane * 4 + 1] = make_float4(aT.y, aM.y, hv.y, 0.f);
            vbase[j * 32 + lane * 4 + 2] = make_float4(aT.z, aM.z, hv.z, 0.f);
            vbase[j * 32 + lane * 4 + 3] = make_float4(aT.w, aM.w, hv.w, 0.f);
        }
    }
    __syncwarp();

    float a0[4], a1[4], p0[4], p1[4];
#pragma unroll
    for (int j = 0; j < 4; j++) { a0[j] = bias0; a1[j] = bias1; p0[j] = 0.f; p1[j] = 0.f; }

#pragma unroll
    for (int ci = 0; ci < 32; ci++) {
        float4 wa = sW4a[ci * 32 + lane];
        float4 wb = sW4b[ci * 32 + lane];
#pragma unroll
        for (int j = 0; j < 4; j++) {
            float4 v = vbase[j * 32 + ci];
            a0[j] += v.x * wa.x + v.y * wa.y + v.z * wa.z;
            p0[j] += v.z * wa.w;
            a1[j] += v.x * wb.x + v.y * wb.y + v.z * wb.z;
            p1[j] += v.z * wb.w;
        }
    }
#pragma unroll
    for (int j = 0; j < 4; j++) {
        int node = node0 + j;
        if (node < n) {
            out[node * 64 + lane]      = fmaxf(a0[j], 0.f) + p0[j];
            out[node * 64 + lane + 32] = fmaxf(a1[j], 0.f) + p1[j];
        }
    }
}

// ---------------------------------------------------------------------------
// Launch
// ---------------------------------------------------------------------------
extern "C" void kernel_launch(void* const* d_in, const int* in_sizes, int n_in,
                              void* d_out, int out_size) {
    const float* x        = (const float*)d_in[0];
    const int*   ei_t     = (const int*)d_in[1];
    const int*   ei_i     = (const int*)d_in[2];
    const float* head_Wt  = (const float*)d_in[3];
    const float* head_Wi  = (const float*)d_in[4];
    const float* head_Wr  = (const float*)d_in[5];
    const float* head_b   = (const float*)d_in[6];
    const float* blk_Wt   = (const float*)d_in[7];
    const float* blk_Wi   = (const float*)d_in[8];
    const float* blk_Wr   = (const float*)d_in[9];
    const float* blk_b    = (const float*)d_in[10];
    const float* last_Wt  = (const float*)d_in[11];
    const float* last_Wi  = (const float*)d_in[12];
    const float* last_Wr  = (const float*)d_in[13];
    const float* last_b   = (const float*)d_in[14];
    const float* last_proj= (const float*)d_in[15];

    const int n  = in_sizes[0] / 6;      // 100000
    const int Et = in_sizes[1] / 2;      // 100000
    const int Ei = in_sizes[2] / 2;      // 3200000

    float *h, *h2, *x8, *dmy;
    int *degt, *degi, *rpt, *rpi, *colt, *coli, *bst, *bsi;
    cudaGetSymbolAddress((void**)&h,    g_h);
    cudaGetSymbolAddress((void**)&h2,   g_h2);
    cudaGetSymbolAddress((void**)&x8,   g_x8);
    cudaGetSymbolAddress((void**)&dmy,  g_dummy);
    cudaGetSymbolAddress((void**)&degt, g_deg_t);
    cudaGetSymbolAddress((void**)&degi, g_deg_i);
    cudaGetSymbolAddress((void**)&rpt,  g_rpt);
    cudaGetSymbolAddress((void**)&rpi,  g_rpi);
    cudaGetSymbolAddress((void**)&bst,  g_bsum_t);
    cudaGetSymbolAddress((void**)&bsi,  g_bsum_i);
    cudaGetSymbolAddress((void**)&colt, g_col_t);
    cudaGetSymbolAddress((void**)&coli, g_col_i);

    const int T = 256;
    int nb = (n + 1023) / 1024;
    int blocks32 = (n + 31) / 32;      // 8 warps x 4 nodes per 256-thread block
    int blocks16 = (n + 15) / 16;      // 4 warps x 4 nodes per 128-thread block

    // Launch 0-2: zero + counts
    zero2_kernel<<<(n + T - 1) / T, T>>>(degt, degi, n);
    count_kernel<<<(Et + T - 1) / T, T>>>(ei_t + Et, Et, degt);
    count_kernel<<<(Ei + T - 1) / T, T>>>(ei_i + Ei, Ei, degi);

    // Launch 3 (ncu capture slot): DUMMY fused_hidden2 on 25k nodes.
    // Reads state persisted from the previous replay (zero-init safe).
    {
        const int nd = 25000;
        fused_hidden2<<<(nd + 31) / 32, T>>>(h, rpt, colt, rpi, coli,
                                             blk_Wt, blk_Wi, blk_Wr, blk_b, dmy, nd);
    }

    repack_x8<<<(n * 8 + T - 1) / T, T>>>(x, x8, n);

    scan_p1<<<nb, 1024>>>(degt, rpt, bst, n);
    scan_p1<<<nb, 1024>>>(degi, rpi, bsi, n);
    scan_p2<<<1, 1024>>>(bst, nb);
    scan_p2<<<1, 1024>>>(bsi, nb);
    scan_p3<<<(n + T) / T, T>>>(rpt, bst, degt, n, Et);
    scan_p3<<<(n + T) / T, T>>>(rpi, bsi, degi, n, Ei);
    fill_kernel<<<(Et + T - 1) / T, T>>>(ei_t, ei_t + Et, Et, degt, colt);
    fill_kernel<<<(Ei + T - 1) / T, T>>>(ei_i, ei_i + Ei, Ei, degi, coli);

    // --- head: 6 -> 32 ---
    fused_head2<<<blocks32, T>>>(x8, rpt, colt, rpi, coli,
                                 head_Wt, head_Wi, head_Wr, head_b, h, n);

    // --- 3 residual blocks: 32 -> 32 ---
    for (int i = 0; i < 3; i++) {
        fused_hidden2<<<blocks32, T>>>(h, rpt, colt, rpi, coli,
                                       blk_Wt + i * 32 * 32, blk_Wi + i * 32 * 32,
                                       blk_Wr + i * 32 * 32, blk_b + i * 32,
                                       h2, n);
        float* tmp = h; h = h2; h2 = tmp;
    }

    // --- last: 32 -> 64 ---
    fused_last2<<<blocks16, 128>>>(h, rpt, colt, rpi, coli,
                                   last_Wt, last_Wi, last_Wr, last_b, last_proj,
                                   (float*)d_out, n);
}

// round 13
// speedup vs baseline: 1.3361x; 1.1018x over previous
#include <cuda_runtime.h>
#include <cuda_fp16.h>

// ---------------------------------------------------------------------------
// Hetero-GNN (5 hetero_conv layers) over N=100000 nodes.
// R13 = R12 (MIO-lean fused layers: float4 edge-group gather + smem-staged
//       combine) retuned for occupancy: 384-thread blocks (12 warps x 4
//       nodes) so the 16KB weight array amortizes and smem/block drops to
//       ~40KB -> ~94% occupancy (was 37.9%).
// ---------------------------------------------------------------------------

#define N_NODES 100000
#define WPB 12                      // warps per block (node kernels)
#define NPB (WPB * 4)               // nodes per block

__device__ float g_h    [N_NODES * 32];
__device__ float g_h2   [N_NODES * 32];
__device__ float g_x8   [N_NODES * 8];
__device__ float g_dummy[N_NODES * 32];

__device__ int g_deg_t[N_NODES];
__device__ int g_deg_i[N_NODES];
__device__ int g_rpt  [N_NODES + 1];
__device__ int g_rpi  [N_NODES + 1];
__device__ int g_bsum_t[1024];
__device__ int g_bsum_i[1024];
__device__ int g_col_t[100000];
__device__ int g_col_i[3200000];

// ---------------------------------------------------------------------------
// CSR build (identical to champion)
// ---------------------------------------------------------------------------
__global__ void zero2_kernel(int* __restrict__ a, int* __restrict__ b, int n) {
    int i = blockIdx.x * blockDim.x + threadIdx.x;
    if (i < n) { a[i] = 0; b[i] = 0; }
}

__global__ void count_kernel(const int* __restrict__ dst, int E, int* __restrict__ deg) {
    int i = blockIdx.x * blockDim.x + threadIdx.x;
    if (i < E) atomicAdd(&deg[dst[i]], 1);
}

__global__ void scan_p1(const int* __restrict__ deg, int* __restrict__ rowptr,
                        int* __restrict__ bsum, int n) {
    __shared__ int sh[1024];
    int i = blockIdx.x * 1024 + threadIdx.x;
    int v = (i < n) ? deg[i] : 0;
    sh[threadIdx.x] = v;
    __syncthreads();
    for (int off = 1; off < 1024; off <<= 1) {
        int t = (threadIdx.x >= off) ? sh[threadIdx.x - off] : 0;
        __syncthreads();
        sh[threadIdx.x] += t;
        __syncthreads();
    }
    if (i < n) rowptr[i] = sh[threadIdx.x] - v;
    if (threadIdx.x == 1023) bsum[blockIdx.x] = sh[1023];
}

__global__ void scan_p2(int* __restrict__ bsum, int nb) {
    __shared__ int sh[1024];
    int v = (threadIdx.x < nb) ? bsum[threadIdx.x] : 0;
    sh[threadIdx.x] = v;
    __syncthreads();
    for (int off = 1; off < 1024; off <<= 1) {
        int t = (threadIdx.x >= off) ? sh[threadIdx.x - off] : 0;
        __syncthreads();
        sh[threadIdx.x] += t;
        __syncthreads();
    }
    if (threadIdx.x < nb) bsum[threadIdx.x] = sh[threadIdx.x] - v;
}

__global__ void scan_p3(int* __restrict__ rowptr, const int* __restrict__ bsum,
                        int* __restrict__ cursor, int n, int E) {
    int i = blockIdx.x * blockDim.x + threadIdx.x;
    if (i < n) {
        int v = rowptr[i] + bsum[i >> 10];
        rowptr[i] = v;
        cursor[i] = v;
    }
    if (i == 0) rowptr[n] = E;
}

__global__ void fill_kernel(const int* __restrict__ src, const int* __restrict__ dst,
                            int E, int* __restrict__ cursor, int* __restrict__ col) {
    int i = blockIdx.x * blockDim.x + threadIdx.x;
    if (i < E) {
        int d = dst[i];
        int p = atomicAdd(&cursor[d], 1);
        col[p] = src[i];
    }
}

__global__ void repack_x8(const float* __restrict__ x, float* __restrict__ x8, int n) {
    int i = blockIdx.x * blockDim.x + threadIdx.x;
    if (i < n * 8) {
        int node = i >> 3, c = i & 7;
        x8[i] = (c < 6) ? x[node * 6 + c] : 0.f;
    }
}

// ---------------------------------------------------------------------------
// Fused HIDDEN layer (32->32, residual). WPB warps x 4 nodes.
// ---------------------------------------------------------------------------
__global__ void __launch_bounds__(WPB * 32)
fused_hidden2(const float* __restrict__ h,
              const int* __restrict__ rpt, const int* __restrict__ colt,
              const int* __restrict__ rpi, const int* __restrict__ coli,
              const float* __restrict__ Wt, const float* __restrict__ Wi,
              const float* __restrict__ Wr, const float* __restrict__ b,
              float* __restrict__ hout, int n) {
    __shared__ float4 sW4[32 * 32];          // 16 KB
    __shared__ float4 sV[WPB * 4 * 32];      // 24 KB
    __shared__ float  sB[32];

    for (int i = threadIdx.x; i < 32 * 32; i += blockDim.x) {
        int ci = i >> 5, l = i & 31;
        sW4[i] = make_float4(Wt[ci * 32 + l], Wi[ci * 32 + l], Wr[ci * 32 + l], 0.f);
    }
    if (threadIdx.x < 32) sB[threadIdx.x] = b[threadIdx.x];
    __syncthreads();

    int warp = threadIdx.x >> 5, lane = threadIdx.x & 31;
    int node0 = (blockIdx.x * WPB + warp) * 4;
    if (node0 >= n) return;
    int g = lane >> 3, c = lane & 7;
    const float4* h4 = (const float4*)h;
    float4* vbase = &sV[warp * 128];

#pragma unroll
    for (int j = 0; j < 4; j++) {
        int node = node0 + j;
        if (node >= n) break;

        float4 aT = make_float4(0.f, 0.f, 0.f, 0.f);
        float4 aM = make_float4(0.f, 0.f, 0.f, 0.f);

        int b0 = rpt[node], e0 = rpt[node + 1];
        for (int e = b0; e < e0; e += 4) {
            int ei = e + g;
            int ec = (ei < e0) ? ei : (e0 - 1);
            int s = colt[ec];
            float4 v = h4[s * 8 + c];
            if (ei < e0) { aT.x += v.x; aT.y += v.y; aT.z += v.z; aT.w += v.w; }
        }

        int b1 = rpi[node], e1 = rpi[node + 1];
        for (int e = b1; e < e1; e += 4) {
            int ei = e + g;
            int ec = (ei < e1) ? ei : (e1 - 1);
            int s = coli[ec];
            float4 v = h4[s * 8 + c];
            if (ei < e1) { aM.x += v.x; aM.y += v.y; aM.z += v.z; aM.w += v.w; }
        }

#pragma unroll
        for (int off = 8; off <= 16; off <<= 1) {
            aT.x += __shfl_xor_sync(0xffffffffu, aT.x, off);
            aT.y += __shfl_xor_sync(0xffffffffu, aT.y, off);
            aT.z += __shfl_xor_sync(0xffffffffu, aT.z, off);
            aT.w += __shfl_xor_sync(0xffffffffu, aT.w, off);
            aM.x += __shfl_xor_sync(0xffffffffu, aM.x, off);
            aM.y += __shfl_xor_sync(0xffffffffu, aM.y, off);
            aM.z += __shfl_xor_sync(0xffffffffu, aM.z, off);
            aM.w += __shfl_xor_sync(0xffffffffu, aM.w, off);
        }
        float invd = 1.0f / fmaxf((float)(e1 - b1), 1.0f);
        aM.x *= invd; aM.y *= invd; aM.z *= invd; aM.w *= invd;

        if (lane < 8) {
            float4 hv = h4[node * 8 + lane];
            vbase[j * 32 + lane * 4 + 0] = make_float4(aT.x, aM.x, hv.x, 0.f);
            vbase[j * 32 + lane * 4 + 1] = make_float4(aT.y, aM.y, hv.y, 0.f);
            vbase[j * 32 + lane * 4 + 2] = make_float4(aT.z, aM.z, hv.z, 0.f);
            vbase[j * 32 + lane * 4 + 3] = make_float4(aT.w, aM.w, hv.w, 0.f);
        }
    }
    __syncwarp();

    float acc0 = sB[lane], acc1 = sB[lane], acc2 = sB[lane], acc3 = sB[lane];
#pragma unroll
    for (int ci = 0; ci < 32; ci++) {
        float4 w = sW4[ci * 32 + lane];
        float4 v0 = vbase[0 * 32 + ci];
        float4 v1 = vbase[1 * 32 + ci];
        float4 v2 = vbase[2 * 32 + ci];
        float4 v3 = vbase[3 * 32 + ci];
        acc0 += v0.x * w.x + v0.y * w.y + v0.z * w.z;
        acc1 += v1.x * w.x + v1.y * w.y + v1.z * w.z;
        acc2 += v2.x * w.x + v2.y * w.y + v2.z * w.z;
        acc3 += v3.x * w.x + v3.y * w.y + v3.z * w.z;
    }
    float accs[4] = {acc0, acc1, acc2, acc3};
#pragma unroll
    for (int j = 0; j < 4; j++) {
        int node = node0 + j;
        if (node < n) {
            float hv = vbase[j * 32 + lane].z;
            hout[node * 32 + lane] = fmaxf(accs[j], 0.f) + hv;
        }
    }
}

// ---------------------------------------------------------------------------
// Fused HEAD layer (6->32). Padded x8 rows; 16 edge-groups x 2 lanes.
// ---------------------------------------------------------------------------
__global__ void __launch_bounds__(WPB * 32)
fused_head2(const float* __restrict__ x8,
            const int* __restrict__ rpt, const int* __restrict__ colt,
            const int* __restrict__ rpi, const int* __restrict__ coli,
            const float* __restrict__ Wt, const float* __restrict__ Wi,
            const float* __restrict__ Wr, const float* __restrict__ b,
            float* __restrict__ hout, int n) {
    __shared__ float4 sW4[6 * 32];
    __shared__ float4 sV[WPB * 4 * 8];
    __shared__ float  sB[32];

    for (int i = threadIdx.x; i < 6 * 32; i += blockDim.x) {
        int ci = i >> 5, l = i & 31;
        sW4[i] = make_float4(Wt[ci * 32 + l], Wi[ci * 32 + l], Wr[ci * 32 + l], 0.f);
    }
    if (threadIdx.x < 32) sB[threadIdx.x] = b[threadIdx.x];
    __syncthreads();

    int warp = threadIdx.x >> 5, lane = threadIdx.x & 31;
    int node0 = (blockIdx.x * WPB + warp) * 4;
    if (node0 >= n) return;
    int g = lane >> 1, c = lane & 1;
    const float4* x4 = (const float4*)x8;
    float4* vbase = &sV[warp * 32];

#pragma unroll
    for (int j = 0; j < 4; j++) {
        int node = node0 + j;
        if (node >= n) break;

        float4 aT = make_float4(0.f, 0.f, 0.f, 0.f);
        float4 aM = make_float4(0.f, 0.f, 0.f, 0.f);

        int b0 = rpt[node], e0 = rpt[node + 1];
        for (int e = b0; e < e0; e += 16) {
            int ei = e + g;
            int ec = (ei < e0) ? ei : (e0 - 1);
            int s = colt[ec];
            float4 v = x4[s * 2 + c];
            if (ei < e0) { aT.x += v.x; aT.y += v.y; aT.z += v.z; aT.w += v.w; }
        }

        int b1 = rpi[node], e1 = rpi[node + 1];
        for (int e = b1; e < e1; e += 16) {
            int ei = e + g;
            int ec = (ei < e1) ? ei : (e1 - 1);
            int s = coli[ec];
            float4 v = x4[s * 2 + c];
            if (ei < e1) { aM.x += v.x; aM.y += v.y; aM.z += v.z; aM.w += v.w; }
        }

#pragma unroll
        for (int off = 2; off <= 16; off <<= 1) {
            aT.x += __shfl_xor_sync(0xffffffffu, aT.x, off);
            aT.y += __shfl_xor_sync(0xffffffffu, aT.y, off);
            aT.z += __shfl_xor_sync(0xffffffffu, aT.z, off);
            aT.w += __shfl_xor_sync(0xffffffffu, aT.w, off);
            aM.x += __shfl_xor_sync(0xffffffffu, aM.x, off);
            aM.y += __shfl_xor_sync(0xffffffffu, aM.y, off);
            aM.z += __shfl_xor_sync(0xffffffffu, aM.z, off);
            aM.w += __shfl_xor_sync(0xffffffffu, aM.w, off);
        }
        float invd = 1.0f / fmaxf((float)(e1 - b1), 1.0f);
        aM.x *= invd; aM.y *= invd; aM.z *= invd; aM.w *= invd;

        if (lane < 2) {
            float4 xv = x4[node * 2 + lane];
            vbase[j * 8 + lane * 4 + 0] = make_float4(aT.x, aM.x, xv.x, 0.f);
            vbase[j * 8 + lane * 4 + 1] = make_float4(aT.y, aM.y, xv.y, 0.f);
            vbase[j * 8 + lane * 4 + 2] = make_float4(aT.z, aM.z, xv.z, 0.f);
            vbase[j * 8 + lane * 4 + 3] = make_float4(aT.w, aM.w, xv.w, 0.f);
        }
    }
    __syncwarp();

    float acc0 = sB[lane], acc1 = sB[lane], acc2 = sB[lane], acc3 = sB[lane];
#pragma unroll
    for (int ci = 0; ci < 6; ci++) {
        float4 w = sW4[ci * 32 + lane];
        float4 v0 = vbase[0 * 8 + ci];
        float4 v1 = vbase[1 * 8 + ci];
        float4 v2 = vbase[2 * 8 + ci];
        float4 v3 = vbase[3 * 8 + ci];
        acc0 += v0.x * w.x + v0.y * w.y + v0.z * w.z;
        acc1 += v1.x * w.x + v1.y * w.y + v1.z * w.z;
        acc2 += v2.x * w.x + v2.y * w.y + v2.z * w.z;
        acc3 += v3.x * w.x + v3.y * w.y + v3.z * w.z;
    }
    float accs[4] = {acc0, acc1, acc2, acc3};
#pragma unroll
    for (int j = 0; j < 4; j++) {
        int node = node0 + j;
        if (node < n) hout[node * 32 + lane] = fmaxf(accs[j], 0.f);
    }
}

// ---------------------------------------------------------------------------
// Fused LAST layer (32->64 + projection residual). WPB warps x 4 nodes.
// ---------------------------------------------------------------------------
__global__ void __launch_bounds__(WPB * 32)
fused_last2(const float* __restrict__ h,
            const int* __restrict__ rpt, const int* __restrict__ colt,
            const int* __restrict__ rpi, const int* __restrict__ coli,
            const float* __restrict__ Wt, const float* __restrict__ Wi,
            const float* __restrict__ Wr, const float* __restrict__ b,
            const float* __restrict__ Wp,
            float* __restrict__ out, int n) {
    __shared__ float4 sW4a[32 * 32];         // 16 KB
    __shared__ float4 sW4b[32 * 32];         // 16 KB
    __shared__ float4 sV[WPB * 4 * 32];      // 24 KB

    for (int i = threadIdx.x; i < 32 * 32; i += blockDim.x) {
        int ci = i >> 5, l = i & 31;
        sW4a[i] = make_float4(Wt[ci * 64 + l],      Wi[ci * 64 + l],      Wr[ci * 64 + l],      Wp[ci * 64 + l]);
        sW4b[i] = make_float4(Wt[ci * 64 + l + 32], Wi[ci * 64 + l + 32], Wr[ci * 64 + l + 32], Wp[ci * 64 + l + 32]);
    }
    __syncthreads();

    int warp = threadIdx.x >> 5, lane = threadIdx.x & 31;
    int node0 = (blockIdx.x * WPB + warp) * 4;
    if (node0 >= n) return;
    int g = lane >> 3, c = lane & 7;
    const float4* h4 = (const float4*)h;
    float4* vbase = &sV[warp * 128];

    float bias0 = b[lane], bias1 = b[lane + 32];

#pragma unroll
    for (int j = 0; j < 4; j++) {
        int node = node0 + j;
        if (node >= n) break;

        float4 aT = make_float4(0.f, 0.f, 0.f, 0.f);
        float4 aM = make_float4(0.f, 0.f, 0.f, 0.f);

        int b0 = rpt[node], e0 = rpt[node + 1];
        for (int e = b0; e < e0; e += 4) {
            int ei = e + g;
            int ec = (ei < e0) ? ei : (e0 - 1);
            int s = colt[ec];
            float4 v = h4[s * 8 + c];
            if (ei < e0) { aT.x += v.x; aT.y += v.y; aT.z += v.z; aT.w += v.w; }
        }

        int b1 = rpi[node], e1 = rpi[node + 1];
        for (int e = b1; e < e1; e += 4) {
            int ei = e + g;
            int ec = (ei < e1) ? ei : (e1 - 1);
            int s = coli[ec];
            float4 v = h4[s * 8 + c];
            if (ei < e1) { aM.x += v.x; aM.y += v.y; aM.z += v.z; aM.w += v.w; }
        }

#pragma unroll
        for (int off = 8; off <= 16; off <<= 1) {
            aT.x += __shfl_xor_sync(0xffffffffu, aT.x, off);
            aT.y += __shfl_xor_sync(0xffffffffu, aT.y, off);
            aT.z += __shfl_xor_sync(0xffffffffu, aT.z, off);
            aT.w += __shfl_xor_sync(0xffffffffu, aT.w, off);
            aM.x += __shfl_xor_sync(0xffffffffu, aM.x, off);
            aM.y += __shfl_xor_sync(0xffffffffu, aM.y, off);
            aM.z += __shfl_xor_sync(0xffffffffu, aM.z, off);
            aM.w += __shfl_xor_sync(0xffffffffu, aM.w, off);
        }
        float invd = 1.0f / fmaxf((float)(e1 - b1), 1.0f);
        aM.x *= invd; aM.y *= invd; aM.z *= invd; aM.w *= invd;

        if (lane < 8) {
            float4 hv = h4[node * 8 + lane];
            vbase[j * 32 + lane * 4 + 0] = make_float4(aT.x, aM.x, hv.x, 0.f);
            vbase[j * 32 + lane * 4 + 1] = make_float4(aT.y, aM.y, hv.y, 0.f);
            vbase[j * 32 + lane * 4 + 2] = make_float4(aT.z, aM.z, hv.z, 0.f);
            vbase[j * 32 + lane * 4 + 3] = make_float4(aT.w, aM.w, hv.w, 0.f);
        }
    }
    __syncwarp();

    float a0[4], a1[4], p0[4], p1[4];
#pragma unroll
    for (int j = 0; j < 4; j++) { a0[j] = bias0; a1[j] = bias1; p0[j] = 0.f; p1[j] = 0.f; }

#pragma unroll
    for (int ci = 0; ci < 32; ci++) {
        float4 wa = sW4a[ci * 32 + lane];
        float4 wb = sW4b[ci * 32 + lane];
#pragma unroll
        for (int j = 0; j < 4; j++) {
            float4 v = vbase[j * 32 + ci];
            a0[j] += v.x * wa.x + v.y * wa.y + v.z * wa.z;
            p0[j] += v.z * wa.w;
            a1[j] += v.x * wb.x + v.y * wb.y + v.z * wb.z;
            p1[j] += v.z * wb.w;
        }
    }
#pragma unroll
    for (int j = 0; j < 4; j++) {
        int node = node0 + j;
        if (node < n) {
            out[node * 64 + lane]      = fmaxf(a0[j], 0.f) + p0[j];
            out[node * 64 + lane + 32] = fmaxf(a1[j], 0.f) + p1[j];
        }
    }
}

// ---------------------------------------------------------------------------
// Launch
// ---------------------------------------------------------------------------
extern "C" void kernel_launch(void* const* d_in, const int* in_sizes, int n_in,
                              void* d_out, int out_size) {
    const float* x        = (const float*)d_in[0];
    const int*   ei_t     = (const int*)d_in[1];
    const int*   ei_i     = (const int*)d_in[2];
    const float* head_Wt  = (const float*)d_in[3];
    const float* head_Wi  = (const float*)d_in[4];
    const float* head_Wr  = (const float*)d_in[5];
    const float* head_b   = (const float*)d_in[6];
    const float* blk_Wt   = (const float*)d_in[7];
    const float* blk_Wi   = (const float*)d_in[8];
    const float* blk_Wr   = (const float*)d_in[9];
    const float* blk_b    = (const float*)d_in[10];
    const float* last_Wt  = (const float*)d_in[11];
    const float* last_Wi  = (const float*)d_in[12];
    const float* last_Wr  = (const float*)d_in[13];
    const float* last_b   = (const float*)d_in[14];
    const float* last_proj= (const float*)d_in[15];

    const int n  = in_sizes[0] / 6;      // 100000
    const int Et = in_sizes[1] / 2;      // 100000
    const int Ei = in_sizes[2] / 2;      // 3200000

    float *h, *h2, *x8, *dmy;
    int *degt, *degi, *rpt, *rpi, *colt, *coli, *bst, *bsi;
    cudaGetSymbolAddress((void**)&h,    g_h);
    cudaGetSymbolAddress((void**)&h2,   g_h2);
    cudaGetSymbolAddress((void**)&x8,   g_x8);
    cudaGetSymbolAddress((void**)&dmy,  g_dummy);
    cudaGetSymbolAddress((void**)&degt, g_deg_t);
    cudaGetSymbolAddress((void**)&degi, g_deg_i);
    cudaGetSymbolAddress((void**)&rpt,  g_rpt);
    cudaGetSymbolAddress((void**)&rpi,  g_rpi);
    cudaGetSymbolAddress((void**)&bst,  g_bsum_t);
    cudaGetSymbolAddress((void**)&bsi,  g_bsum_i);
    cudaGetSymbolAddress((void**)&colt, g_col_t);
    cudaGetSymbolAddress((void**)&coli, g_col_i);

    const int T = 256;
    const int TB = WPB * 32;           // 384
    int nb = (n + 1023) / 1024;
    int nodeBlocks = (n + NPB - 1) / NPB;

    // Launch 0-2: zero + counts
    zero2_kernel<<<(n + T - 1) / T, T>>>(degt, degi, n);
    count_kernel<<<(Et + T - 1) / T, T>>>(ei_t + Et, Et, degt);
    count_kernel<<<(Ei + T - 1) / T, T>>>(ei_i + Ei, Ei, degi);

    // Launch 3 (ncu capture slot): DUMMY fused_hidden2 on 12.5k nodes.
    {
        const int nd = 12500;
        fused_hidden2<<<(nd + NPB - 1) / NPB, TB>>>(h, rpt, colt, rpi, coli,
                                                    blk_Wt, blk_Wi, blk_Wr, blk_b,
                                                    dmy, nd);
    }

    repack_x8<<<(n * 8 + T - 1) / T, T>>>(x, x8, n);

    scan_p1<<<nb, 1024>>>(degt, rpt, bst, n);
    scan_p1<<<nb, 1024>>>(degi, rpi, bsi, n);
    scan_p2<<<1, 1024>>>(bst, nb);
    scan_p2<<<1, 1024>>>(bsi, nb);
    scan_p3<<<(n + T) / T, T>>>(rpt, bst, degt, n, Et);
    scan_p3<<<(n + T) / T, T>>>(rpi, bsi, degi, n, Ei);
    fill_kernel<<<(Et + T - 1) / T, T>>>(ei_t, ei_t + Et, Et, degt, colt);
    fill_kernel<<<(Ei + T - 1) / T, T>>>(ei_i, ei_i + Ei, Ei, degi, coli);

    // --- head: 6 -> 32 ---
    fused_head2<<<nodeBlocks, TB>>>(x8, rpt, colt, rpi, coli,
                                    head_Wt, head_Wi, head_Wr, head_b, h, n);

    // --- 3 residual blocks: 32 -> 32 ---
    for (int i = 0; i < 3; i++) {
        fused_hidden2<<<nodeBlocks, TB>>>(h, rpt, colt, rpi, coli,
                                          blk_Wt + i * 32 * 32, blk_Wi + i * 32 * 32,
                                          blk_Wr + i * 32 * 32, blk_b + i * 32,
                                          h2, n);
        float* tmp = h; h = h2; h2 = tmp;
    }

    // --- last: 32 -> 64 ---
    fused_last2<<<nodeBlocks, TB>>>(h, rpt, colt, rpi, coli,
                                    last_Wt, last_Wi, last_Wr, last_b, last_proj,
                                    (float*)d_out, n);
}